// round 15
// baseline (speedup 1.0000x reference)
#include <cuda_runtime.h>
#include <cuda_fp16.h>
#include <math_constants.h>

#define NNODES 100000
#define FIN 512
#define F1 16
#define F2P 8   // 7 padded to 8

// ---------------- scratch (no allocations allowed) ----------------
__device__ __align__(16) float  g_deg[NNODES];            // degree incl. self-loop
__device__ __align__(16) __half g_y1[NNODES * F1];        // f16 gather src (32B/row)
__device__ __align__(16) __half g_acc1[NNODES * F1];      // f16 RED accumulator
__device__ __align__(16) __half g_y2[NNODES * F2P];       // 16B/row
__device__ __align__(16) __half g_acc2[NNODES * F2P];
__device__ int g_is64;   // edge dtype flag (1 = int64, 0 = int32)

// ---------------- helpers ----------------
__device__ __forceinline__ void red_v4h(__half* p, uint4 v) {
    asm volatile("red.global.add.noftz.v4.f16x2 [%0], {%1, %2, %3, %4};"
                 :: "l"(p), "r"(v.x), "r"(v.y), "r"(v.z), "r"(v.w) : "memory");
}
__device__ __forceinline__ unsigned long long fma2(unsigned long long a,
                                                   unsigned long long b,
                                                   unsigned long long c) {
    unsigned long long d;
    asm("fma.rn.f32x2 %0, %1, %2, %3;" : "=l"(d) : "l"(a), "l"(b), "l"(c));
    return d;
}
__device__ __forceinline__ unsigned long long mul2(unsigned long long a,
                                                   unsigned long long b) {
    unsigned long long d;
    asm("mul.rn.f32x2 %0, %1, %2;" : "=l"(d) : "l"(a), "l"(b));
    return d;
}
__device__ __forceinline__ unsigned long long pack2(float x) {
    unsigned long long d;
    unsigned xi = __float_as_uint(x);
    asm("mov.b64 %0, {%1, %1};" : "=l"(d) : "r"(xi));
    return d;
}
__device__ __forceinline__ unsigned h2_from_u64(unsigned long long v) {
    unsigned lo, hi;
    asm("mov.b64 {%0, %1}, %2;" : "=r"(lo), "=r"(hi) : "l"(v));
    __half2 h = __floats2half2_rn(__uint_as_float(lo), __uint_as_float(hi));
    return *(unsigned*)&h;
}

// Layout: planar [all sources | all targets], E entries per block.
__device__ __forceinline__ void load_edge(const void* ei, int E, int e,
                                          int& r, int& c) {
    if (g_is64) {
        const long long* p = (const long long*)ei;
        r = (int)p[e];
        c = (int)p[(size_t)E + e];
    } else {
        const int* p = (const int*)ei;
        r = p[e];
        c = p[(size_t)E + e];
    }
}

// paired edge load for edges (e0, e0+1); e0 even. Valid only when E even.
__device__ __forceinline__ void load_edge_pair(const void* ei, int E, int e0,
                                               int& r0, int& c0, int& r1, int& c1) {
    if (g_is64) {
        const long long* p = (const long long*)ei;
        longlong2 rv = *(const longlong2*)(p + e0);
        longlong2 cv = *(const longlong2*)(p + (size_t)E + e0);
        r0 = (int)rv.x; r1 = (int)rv.y;
        c0 = (int)cv.x; c1 = (int)cv.y;
    } else {
        const int* p = (const int*)ei;
        int2 rv = *(const int2*)(p + e0);
        int2 cv = *(const int2*)(p + (size_t)E + e0);
        r0 = rv.x; r1 = rv.y;
        c0 = cv.x; c1 = cv.y;
    }
}
__device__ __forceinline__ int load_col(const void* ei, int E, int e) {
    if (g_is64) return (int)((const long long*)ei)[(size_t)E + e];
    return ((const int*)ei)[(size_t)E + e];
}

// ---------------- kernels ----------------

// fused: dtype probe (global thread 0) + degree init (self-loop = 1).
__global__ void k_setup(const void* ei, int n) {
    int i = blockIdx.x * blockDim.x + threadIdx.x;
    if (i == 0) {
        const long long* p = (const long long*)ei;
        int ok = 1;
        for (int j = 0; j < 64; j++) {
            long long v = p[j];
            if (v < 0 || v >= (long long)n) { ok = 0; break; }
        }
        g_is64 = ok;
    }
    if (i < n) g_deg[i] = 1.0f;
}

// degree: 2 cols per thread (paired index load)
__global__ void k_deg(const void* __restrict__ ei, int E, int n) {
    int t = blockIdx.x * blockDim.x + threadIdx.x;
    int e0 = t * 2;
    if (e0 >= E) return;
    if (((E & 1) == 0) && e0 + 1 < E) {
        int c0, c1;
        if (g_is64) {
            longlong2 cv = *(const longlong2*)((const long long*)ei + (size_t)E + e0);
            c0 = (int)cv.x; c1 = (int)cv.y;
        } else {
            int2 cv = *(const int2*)((const int*)ei + (size_t)E + e0);
            c0 = cv.x; c1 = cv.y;
        }
        if ((unsigned)c0 < (unsigned)n) atomicAdd(&g_deg[c0], 1.0f);
        if ((unsigned)c1 < (unsigned)n) atomicAdd(&g_deg[c1], 1.0f);
    } else {
        for (int e = e0; e < E && e < e0 + 2; e++) {
            int c = load_col(ei, E, e);
            if ((unsigned)c < (unsigned)n) atomicAdd(&g_deg[c], 1.0f);
        }
    }
}

// y1 = rsqrt(deg[row]) * (x @ W1) in f16, dual-stored.
// x staged through smem in 16-float k-chunks for coalesced global loads
// (8 wavefronts/instr vs 32 in thread-per-row direct reads).
// sX row stride = 5 float4 (20 words): conflict-free per 8-lane phase.
__global__ void __launch_bounds__(128) k_gemm1(const float* __restrict__ x,
                                               const float* __restrict__ W,
                                               int n) {
    __shared__ __align__(16) unsigned long long sW[FIN * 8];  // 32 KB
    __shared__ __align__(16) float4 sX[128 * 5];              // 10 KB
    {
        const ulonglong2* Wv = (const ulonglong2*)W;
        ulonglong2* sWv = (ulonglong2*)sW;
        for (int i = threadIdx.x; i < FIN * 4; i += 128) sWv[i] = Wv[i];
    }

    int row0 = blockIdx.x * 128;
    int row = row0 + threadIdx.x;

    unsigned long long acc[8];
#pragma unroll
    for (int f = 0; f < 8; f++) acc[f] = 0ull;

#pragma unroll 1
    for (int ch = 0; ch < FIN / 16; ch++) {
        __syncthreads();   // first iter also fences sW
        // cooperative coalesced load: 128 rows x 4 float4 (16 floats)
#pragma unroll
        for (int i = 0; i < 4; i++) {
            int idx = i * 128 + threadIdx.x;
            int r = idx >> 2, j = idx & 3;
            int gr = row0 + r;
            float4 v = make_float4(0.f, 0.f, 0.f, 0.f);
            if (gr < n) v = *(const float4*)(x + (size_t)gr * FIN + ch * 16 + j * 4);
            sX[r * 5 + j] = v;
        }
        __syncthreads();
#pragma unroll
        for (int kk = 0; kk < 4; kk++) {
            float4 xv = sX[threadIdx.x * 5 + kk];
#pragma unroll
            for (int d = 0; d < 4; d++) {
                float xk = (d == 0) ? xv.x : (d == 1) ? xv.y : (d == 2) ? xv.z : xv.w;
                unsigned long long xx = pack2(xk);
                const ulonglong2* wp =
                    (const ulonglong2*)&sW[(ch * 16 + kk * 4 + d) * 8];
                ulonglong2 wa = wp[0], wb = wp[1];
                acc[0] = fma2(xx, wa.x, acc[0]);
                acc[1] = fma2(xx, wa.y, acc[1]);
                acc[2] = fma2(xx, wb.x, acc[2]);
                acc[3] = fma2(xx, wb.y, acc[3]);
                ulonglong2 wc = wp[2], wd = wp[3];
                acc[4] = fma2(xx, wc.x, acc[4]);
                acc[5] = fma2(xx, wc.y, acc[5]);
                acc[6] = fma2(xx, wd.x, acc[6]);
                acc[7] = fma2(xx, wd.y, acc[7]);
            }
        }
    }

    if (row >= n) return;
    unsigned long long dd = pack2(rsqrtf(g_deg[row]));
    uint4 a, b;
    a.x = h2_from_u64(mul2(acc[0], dd));
    a.y = h2_from_u64(mul2(acc[1], dd));
    a.z = h2_from_u64(mul2(acc[2], dd));
    a.w = h2_from_u64(mul2(acc[3], dd));
    b.x = h2_from_u64(mul2(acc[4], dd));
    b.y = h2_from_u64(mul2(acc[5], dd));
    b.z = h2_from_u64(mul2(acc[6], dd));
    b.w = h2_from_u64(mul2(acc[7], dd));
    uint4* o1 = (uint4*)(g_y1 + (size_t)row * F1);
    uint4* o2 = (uint4*)(g_acc1 + (size_t)row * F1);
    o1[0] = a; o1[1] = b;
    o2[0] = a; o2[1] = b;
}

// layer-1 edge scatter, 2 EDGES PER THREAD (paired index loads).
__global__ void k_scatter1(const void* __restrict__ ei, int E, int n) {
    int t = blockIdx.x * blockDim.x + threadIdx.x;
    int e0 = t * 2;
    if (e0 >= E) return;
    int r0 = -1, c0 = -1, r1 = -1, c1 = -1;
    if (((E & 1) == 0) && e0 + 1 < E) {
        load_edge_pair(ei, E, e0, r0, c0, r1, c1);
    } else {
        load_edge(ei, E, e0, r0, c0);
        if (e0 + 1 < E) load_edge(ei, E, e0 + 1, r1, c1);
    }
    if ((unsigned)r0 < (unsigned)n && (unsigned)c0 < (unsigned)n) {
        const uint4* src = (const uint4*)(g_y1 + (size_t)r0 * F1);
        __half* dst = g_acc1 + (size_t)c0 * F1;
        uint4 a = src[0], b = src[1];
        red_v4h(dst, a);
        red_v4h(dst + 8, b);
    }
    if ((unsigned)r1 < (unsigned)n && (unsigned)c1 < (unsigned)n) {
        const uint4* src = (const uint4*)(g_y1 + (size_t)r1 * F1);
        __half* dst = g_acc1 + (size_t)c1 * F1;
        uint4 a = src[0], b = src[1];
        red_v4h(dst, a);
        red_v4h(dst + 8, b);
    }
}

// h = relu(b1 + dinv*acc1); y2 = dinv*(h @ W2) in f16; dual store.
__global__ void k_layer2(const float* __restrict__ W2,
                         const float* __restrict__ b1, int n) {
    int i = blockIdx.x * blockDim.x + threadIdx.x;
    if (i >= n) return;
    float di = rsqrtf(g_deg[i]);
    const uint4* p = (const uint4*)(g_acc1 + (size_t)i * F1);
    uint4 pa = p[0], pb = p[1];
    float h[16];
    {
        unsigned u[8] = {pa.x, pa.y, pa.z, pa.w, pb.x, pb.y, pb.z, pb.w};
#pragma unroll
        for (int q = 0; q < 8; q++) {
            float2 v = __half22float2(*(__half2*)&u[q]);
            h[q * 2 + 0] = fmaxf(__ldg(&b1[q * 2 + 0]) + di * v.x, 0.f);
            h[q * 2 + 1] = fmaxf(__ldg(&b1[q * 2 + 1]) + di * v.y, 0.f);
        }
    }
    float s[7] = {0.f, 0.f, 0.f, 0.f, 0.f, 0.f, 0.f};
#pragma unroll
    for (int k = 0; k < 16; k++) {
        float hk = h[k];
#pragma unroll
        for (int f = 0; f < 7; f++) s[f] += hk * __ldg(&W2[k * 7 + f]);
    }
    uint4 o;
    {
        __half2 h0 = __floats2half2_rn(di * s[0], di * s[1]);
        __half2 h1 = __floats2half2_rn(di * s[2], di * s[3]);
        __half2 h2 = __floats2half2_rn(di * s[4], di * s[5]);
        __half2 h3 = __floats2half2_rn(di * s[6], 0.f);
        o.x = *(unsigned*)&h0; o.y = *(unsigned*)&h1;
        o.z = *(unsigned*)&h2; o.w = *(unsigned*)&h3;
    }
    *(uint4*)(g_y2 + (size_t)i * F2P) = o;
    *(uint4*)(g_acc2 + (size_t)i * F2P) = o;
}

// layer-2 edge scatter, 2 EDGES PER THREAD.
__global__ void k_scatter2(const void* __restrict__ ei, int E, int n) {
    int t = blockIdx.x * blockDim.x + threadIdx.x;
    int e0 = t * 2;
    if (e0 >= E) return;
    int r0 = -1, c0 = -1, r1 = -1, c1 = -1;
    if (((E & 1) == 0) && e0 + 1 < E) {
        load_edge_pair(ei, E, e0, r0, c0, r1, c1);
    } else {
        load_edge(ei, E, e0, r0, c0);
        if (e0 + 1 < E) load_edge(ei, E, e0 + 1, r1, c1);
    }
    if ((unsigned)r0 < (unsigned)n && (unsigned)c0 < (unsigned)n) {
        uint4 v = *(const uint4*)(g_y2 + (size_t)r0 * F2P);
        red_v4h(g_acc2 + (size_t)c0 * F2P, v);
    }
    if ((unsigned)r1 < (unsigned)n && (unsigned)c1 < (unsigned)n) {
        uint4 v = *(const uint4*)(g_y2 + (size_t)r1 * F2P);
        red_v4h(g_acc2 + (size_t)c1 * F2P, v);
    }
}

// w = b2 + dinv*acc2; log_softmax
__global__ void k_logsoftmax(const float* __restrict__ b2,
                             float* __restrict__ out, int n) {
    int i = blockIdx.x * blockDim.x + threadIdx.x;
    if (i >= n) return;
    float di = rsqrtf(g_deg[i]);
    uint4 v = *(const uint4*)(g_acc2 + (size_t)i * F2P);
    unsigned u[4] = {v.x, v.y, v.z, v.w};
    float w[8];
#pragma unroll
    for (int q = 0; q < 4; q++) {
        float2 f = __half22float2(*(__half2*)&u[q]);
        w[q * 2 + 0] = f.x;
        w[q * 2 + 1] = f.y;
    }
#pragma unroll
    for (int f = 0; f < 7; f++) w[f] = __ldg(&b2[f]) + di * w[f];
    float m = w[0];
#pragma unroll
    for (int f = 1; f < 7; f++) m = fmaxf(m, w[f]);
    float s = 0.f;
#pragma unroll
    for (int f = 0; f < 7; f++) s += expf(w[f] - m);
    float l = logf(s);
    float* o = out + (size_t)i * 7;
#pragma unroll
    for (int f = 0; f < 7; f++) o[f] = w[f] - m - l;
}

// ---------------- launch ----------------
// Inputs identified BY ELEMENT COUNT (x largest, edge_index second largest,
// W1=8192, W2=112, b1=16, b2=7); positional fallback otherwise.
extern "C" void kernel_launch(void* const* d_in, const int* in_sizes, int n_in,
                              void* d_out, int out_size) {
    const void* x  = d_in[0];
    const void* ei = d_in[1];
    const void* W1 = d_in[2];
    const void* b1 = d_in[3];
    const void* W2 = d_in[4];
    const void* b2 = d_in[5];
    int x_sz = in_sizes[0], e_sz = in_sizes[1];

    if (n_in >= 6) {
        int ix = 0;
        for (int i = 1; i < n_in; i++) if (in_sizes[i] > in_sizes[ix]) ix = i;
        int ie = (ix == 0) ? 1 : 0;
        for (int i = 0; i < n_in; i++)
            if (i != ix && in_sizes[i] > in_sizes[ie]) ie = i;
        x = d_in[ix]; x_sz = in_sizes[ix];
        ei = d_in[ie]; e_sz = in_sizes[ie];
        for (int i = 0; i < n_in; i++) {
            if (i == ix || i == ie) continue;
            switch (in_sizes[i]) {
                case 8192: W1 = d_in[i]; break;   // 512*16
                case 112:  W2 = d_in[i]; break;   // 16*7
                case 16:   b1 = d_in[i]; break;
                case 7:    b2 = d_in[i]; break;
                default: break;
            }
        }
    }

    int n = x_sz / FIN;   // 100000
    int E = e_sz / 2;     // 3200000 edges (planar [src | dst])

    const int T = 256;
    int gbN  = (n + T - 1) / T;
    int gbG  = (n + 127) / 128;                  // gemm: 128-thread blocks
    int gbE2 = ((E + 1) / 2 + T - 1) / T;        // 2 edges/thread

    k_setup<<<gbN, T>>>(ei, n);
    k_deg<<<gbE2, T>>>(ei, E, n);
    k_gemm1<<<gbG, 128>>>((const float*)x, (const float*)W1, n);
    k_scatter1<<<gbE2, T>>>(ei, E, n);
    k_layer2<<<gbN, T>>>((const float*)W2, (const float*)b1, n);
    k_scatter2<<<gbE2, T>>>(ei, E, n);
    k_logsoftmax<<<gbN, T>>>((const float*)b2, (float*)d_out, n);
}